// round 13
// baseline (speedup 1.0000x reference)
#include <cuda_runtime.h>
#include <cuda_bf16.h>
#include <cstdint>

// costs[0,i,j] = 0.5*(|x_i|^2 + |y_j|^2) - x_i . y_j
// x: [1,4096,128] f32, y: [1,4096,128] f32, out: [1,4096,4096] f32.
//
// bf16 mma.sync m16n8k16 + ldmatrix, swizzled smem, pre-converted bf16
// operands, 256 thr / 8 warps x (64x32), register-lean loop, 3 CTAs/SM.

#define NROWS 4096
#define DK    128
#define TILE  128

static __device__ float g_x2[NROWS];
static __device__ float g_y2[NROWS];
static __device__ __align__(16) __nv_bfloat16 g_xb[NROWS * DK];
static __device__ __align__(16) __nv_bfloat16 g_yb[NROWS * DK];

// ---- helpers ----
__device__ __forceinline__ uint32_t pack_bf16x2(float a, float b) {
    uint32_t r;
    asm("cvt.rn.bf16x2.f32 %0, %1, %2;" : "=r"(r) : "f"(b), "f"(a));
    return r;
}

__device__ __forceinline__ uint32_t smem_u32(const void* p) {
    uint32_t a;
    asm("{ .reg .u64 t; cvta.to.shared.u64 t, %1; cvt.u32.u64 %0, t; }" : "=r"(a) : "l"(p));
    return a;
}

__device__ __forceinline__ void ldsm4(uint32_t* r, uint32_t addr) {
    asm volatile("ldmatrix.sync.aligned.m8n8.x4.shared.b16 {%0,%1,%2,%3}, [%4];"
                 : "=r"(r[0]), "=r"(r[1]), "=r"(r[2]), "=r"(r[3]) : "r"(addr));
}

__device__ __forceinline__ void mma16(float* d, const uint32_t* a, uint32_t b0, uint32_t b1) {
    asm volatile(
        "mma.sync.aligned.m16n8k16.row.col.f32.bf16.bf16.f32 "
        "{%0,%1,%2,%3}, {%4,%5,%6,%7}, {%8,%9}, {%0,%1,%2,%3};"
        : "+f"(d[0]), "+f"(d[1]), "+f"(d[2]), "+f"(d[3])
        : "r"(a[0]), "r"(a[1]), "r"(a[2]), "r"(a[3]), "r"(b0), "r"(b1));
}

__device__ __forceinline__ void cp16(uint32_t dst, const void* src) {
    asm volatile("cp.async.cg.shared.global [%0], [%1], 16;" :: "r"(dst), "l"(src) : "memory");
}

// ---- smem layout (bytes) ----
#define SM_YS    0
#define SM_A     512
#define SM_B     (512 + TILE * 256)
#define SM_TOTAL (512 + 2 * TILE * 256)

// ---- pre-kernel: row norms + bf16 conversion (one pass) ----
__global__ void prep_kernel(const float* __restrict__ x, const float* __restrict__ y) {
    int gid = blockIdx.x * blockDim.x + threadIdx.x;
    int row = gid >> 5;
    int lane = gid & 31;
    bool isx = row < NROWS;
    int r = isx ? row : row - NROWS;
    const float4 v = ((const float4*)(isx ? x : y))[(size_t)r * 32 + lane];
    float s = v.x * v.x + v.y * v.y + v.z * v.z + v.w * v.w;
#pragma unroll
    for (int o = 16; o; o >>= 1) s += __shfl_xor_sync(0xffffffffu, s, o);
    uint2 w;
    w.x = pack_bf16x2(v.x, v.y);
    w.y = pack_bf16x2(v.z, v.w);
    ((uint2*)(isx ? g_xb : g_yb))[(size_t)r * 32 + lane] = w;
    if (lane == 0) { if (isx) g_x2[r] = s; else g_y2[r] = s; }
}

// ---- main kernel: 128x128 tile/CTA, 8 warps (2M x 4N of 64x32), 3 CTAs/SM ----
__global__ void __launch_bounds__(256, 3)
cost_kernel(float* __restrict__ out) {
    extern __shared__ char smem[];
    float* ys = (float*)(smem + SM_YS);
    const uint32_t smem_base = smem_u32(smem);

    const int tid = threadIdx.x;
    const int wid = tid >> 5;
    const int lane = tid & 31;

    const int m0 = blockIdx.y * TILE;
    const int n0 = blockIdx.x * TILE;

    if (tid < 128) ys[tid] = 0.5f * g_y2[n0 + tid];

    // One-shot fill via cp.async: 4096 16B units, 256 thr -> 16 each.
#pragma unroll
    for (int it = 0; it < 16; it++) {
        int flat = tid + 256 * it;                 // 0..4095
        int isB  = flat >> 11;
        int u    = flat & 2047;
        int row  = u >> 4;                         // 0..127
        int cu   = u & 15;
        const uint4* src = (const uint4*)(isB ? g_yb : g_xb)
                           + (size_t)((isB ? n0 : m0) + row) * 16 + cu;
        uint32_t dst = smem_base + (isB ? SM_B : SM_A) + row * 256 + ((cu ^ (row & 7)) << 4);
        cp16(dst, src);
    }
    asm volatile("cp.async.commit_group;" ::: "memory");
    asm volatile("cp.async.wait_group 0;" ::: "memory");
    __syncthreads();

    // Warp tiling: w_m 0..1 (64 rows), w_n 0..3 (32 cols)
    const int w_m = wid >> 2, w_n = wid & 3;

    const int a_row0 = w_m * 64 + (lane & 7) + ((lane >> 3) & 1) * 8;
    const int a_sel  = lane >> 4;
    const int b_row0 = w_n * 32 + (lane & 7) + (lane >> 4) * 8;
    const int b_sel  = (lane >> 3) & 1;

    const uint32_t aBase = smem_base + SM_A + a_row0 * 256;
    const uint32_t bBase0 = smem_base + SM_B + b_row0 * 256;
    const int a_ph = a_row0 & 7;
    const int b_ph = b_row0 & 7;

    float acc[4][4][4];
#pragma unroll
    for (int ti = 0; ti < 4; ti++)
#pragma unroll
        for (int j = 0; j < 4; j++)
#pragma unroll
            for (int r = 0; r < 4; r++) acc[ti][j][r] = 0.f;

    // Register-lean mainloop: per ks load b0,b1 then stream a per-ti.
#pragma unroll
    for (int ks = 0; ks < 8; ks++) {
        const uint32_t aoff = (uint32_t)(((ks * 2 + a_sel) ^ a_ph) << 4);
        const uint32_t boff = (uint32_t)(((ks * 2 + b_sel) ^ b_ph) << 4);
        uint32_t b0[4], b1[4];
        ldsm4(b0, bBase0 + boff);
        ldsm4(b1, bBase0 + 16 * 256 + boff);
#pragma unroll
        for (int ti = 0; ti < 4; ti++) {
            uint32_t a[4];
            ldsm4(a, aBase + ti * (16 * 256) + aoff);
            mma16(acc[ti][0], a, b0[0], b0[1]);
            mma16(acc[ti][1], a, b0[2], b0[3]);
            mma16(acc[ti][2], a, b1[0], b1[1]);
            mma16(acc[ti][3], a, b1[2], b1[3]);
        }
    }

    // Epilogue: acc[ti][j] -> rows w_m*64+ti*16+{0,8}+gid, cols w_n*32+j*8+2*tig
    const int gid = lane >> 2, tig = lane & 3;
    const int mrow_base = m0 + w_m * 64;

#pragma unroll
    for (int ti = 0; ti < 4; ti++) {
#pragma unroll
        for (int h = 0; h < 2; h++) {
            const int m = mrow_base + ti * 16 + h * 8 + gid;
            const float xv = 0.5f * g_x2[m];
            float* orow = out + (size_t)m * NROWS + n0 + w_n * 32 + tig * 2;
#pragma unroll
            for (int j = 0; j < 4; j++) {
                const int col = w_n * 32 + j * 8 + tig * 2;
                float2 o;
                o.x = xv + ys[col + 0] - acc[ti][j][h * 2 + 0];
                o.y = xv + ys[col + 1] - acc[ti][j][h * 2 + 1];
                *(float2*)(orow + j * 8) = o;
            }
        }
    }
}

// ---- launch ----
extern "C" void kernel_launch(void* const* d_in, const int* in_sizes, int n_in,
                              void* d_out, int out_size) {
    const float* x = (const float*)d_in[0];
    const float* y = (const float*)d_in[1];
    float* out = (float*)d_out;

    cudaFuncSetAttribute(cost_kernel, cudaFuncAttributeMaxDynamicSharedMemorySize, SM_TOTAL);

    prep_kernel<<<(2 * NROWS * 32) / 256, 256>>>(x, y);
    dim3 grid(NROWS / TILE, NROWS / TILE);
    cost_kernel<<<grid, 256, SM_TOTAL>>>(out);
}

// round 15
// speedup vs baseline: 1.1036x; 1.1036x over previous
#include <cuda_runtime.h>
#include <cuda_bf16.h>
#include <cstdint>

// costs[0,i,j] = 0.5*(|x_i|^2 + |y_j|^2) - x_i . y_j
// x: [1,4096,128] f32, y: [1,4096,128] f32, out: [1,4096,4096] f32.
//
// bf16 mma.sync m16n8k16 + ldmatrix, swizzled smem, pre-converted bf16.
// Strip-mined: each CTA does a 128x512 strip (4 n-tiles), A loaded once,
// B double-buffered via cp.async prefetch. 256 CTAs = one wave at 2 CTAs/SM.

#define NROWS 4096
#define DK    128
#define TILE  128

static __device__ float g_x2[NROWS];
static __device__ float g_y2[NROWS];
static __device__ __align__(16) __nv_bfloat16 g_xb[NROWS * DK];
static __device__ __align__(16) __nv_bfloat16 g_yb[NROWS * DK];

// ---- helpers ----
__device__ __forceinline__ uint32_t pack_bf16x2(float a, float b) {
    uint32_t r;
    asm("cvt.rn.bf16x2.f32 %0, %1, %2;" : "=r"(r) : "f"(b), "f"(a));
    return r;
}

__device__ __forceinline__ uint32_t smem_u32(const void* p) {
    uint32_t a;
    asm("{ .reg .u64 t; cvta.to.shared.u64 t, %1; cvt.u32.u64 %0, t; }" : "=r"(a) : "l"(p));
    return a;
}

__device__ __forceinline__ void ldsm4(uint32_t* r, uint32_t addr) {
    asm volatile("ldmatrix.sync.aligned.m8n8.x4.shared.b16 {%0,%1,%2,%3}, [%4];"
                 : "=r"(r[0]), "=r"(r[1]), "=r"(r[2]), "=r"(r[3]) : "r"(addr));
}

__device__ __forceinline__ void mma16(float* d, const uint32_t* a, uint32_t b0, uint32_t b1) {
    asm volatile(
        "mma.sync.aligned.m16n8k16.row.col.f32.bf16.bf16.f32 "
        "{%0,%1,%2,%3}, {%4,%5,%6,%7}, {%8,%9}, {%0,%1,%2,%3};"
        : "+f"(d[0]), "+f"(d[1]), "+f"(d[2]), "+f"(d[3])
        : "r"(a[0]), "r"(a[1]), "r"(a[2]), "r"(a[3]), "r"(b0), "r"(b1));
}

__device__ __forceinline__ void cp16(uint32_t dst, const void* src) {
    asm volatile("cp.async.cg.shared.global [%0], [%1], 16;" :: "r"(dst), "l"(src) : "memory");
}

// ---- smem layout (bytes) ----
// ys: 512 f32 @0 ; A tile @2048 (32KB) ; B buf0 @34816 ; B buf1 @67584.
#define SM_YS    0
#define SM_A     2048
#define SM_B0    (SM_A + TILE * 256)
#define SM_B1    (SM_B0 + TILE * 256)
#define SM_TOTAL (SM_B1 + TILE * 256)     // 100352 B -> 2 CTAs/SM

// ---- pre-kernel: row norms + bf16 conversion (one pass) ----
__global__ void prep_kernel(const float* __restrict__ x, const float* __restrict__ y) {
    int gid = blockIdx.x * blockDim.x + threadIdx.x;
    int row = gid >> 5;
    int lane = gid & 31;
    bool isx = row < NROWS;
    int r = isx ? row : row - NROWS;
    const float4 v = ((const float4*)(isx ? x : y))[(size_t)r * 32 + lane];
    float s = v.x * v.x + v.y * v.y + v.z * v.z + v.w * v.w;
#pragma unroll
    for (int o = 16; o; o >>= 1) s += __shfl_xor_sync(0xffffffffu, s, o);
    uint2 w;
    w.x = pack_bf16x2(v.x, v.y);
    w.y = pack_bf16x2(v.z, v.w);
    ((uint2*)(isx ? g_xb : g_yb))[(size_t)r * 32 + lane] = w;
    if (lane == 0) { if (isx) g_x2[r] = s; else g_y2[r] = s; }
}

// ---- main kernel: 128x512 strip/CTA, 8 warps (2M x 4N of 64x32) ----
__global__ void __launch_bounds__(256, 2)
cost_kernel(float* __restrict__ out) {
    extern __shared__ char smem[];
    float* ys = (float*)(smem + SM_YS);
    const uint32_t smem_base = smem_u32(smem);

    const int tid = threadIdx.x;
    const int wid = tid >> 5;
    const int lane = tid & 31;

    const int m0  = blockIdx.y * TILE;     // 0..31 -> rows
    const int nb0 = blockIdx.x * 512;      // 0..7  -> col strip

    ys[tid]       = 0.5f * g_y2[nb0 + tid];
    ys[tid + 256] = 0.5f * g_y2[nb0 + 256 + tid];

    // Fill A (once) + B tile 0, one cp.async group.
#pragma unroll
    for (int it = 0; it < 8; it++) {
        int u = tid + 256 * it;                // 0..2047
        int row = u >> 4, cu = u & 15;
        const uint4* src = (const uint4*)g_xb + (size_t)(m0 + row) * 16 + cu;
        cp16(smem_base + SM_A + row * 256 + ((cu ^ (row & 7)) << 4), src);
    }
#pragma unroll
    for (int it = 0; it < 8; it++) {
        int u = tid + 256 * it;
        int row = u >> 4, cu = u & 15;
        const uint4* src = (const uint4*)g_yb + (size_t)(nb0 + row) * 16 + cu;
        cp16(smem_base + SM_B0 + row * 256 + ((cu ^ (row & 7)) << 4), src);
    }
    asm volatile("cp.async.commit_group;" ::: "memory");

    // Warp tiling within a 128x128 tile: w_m 0..1 (64 rows), w_n 0..3 (32 cols)
    const int w_m = wid >> 2, w_n = wid & 3;

    const int a_row0 = w_m * 64 + (lane & 7) + ((lane >> 3) & 1) * 8;
    const int a_sel  = lane >> 4;
    const int b_row0 = w_n * 32 + (lane & 7) + (lane >> 4) * 8;
    const int b_sel  = (lane >> 3) & 1;

    const uint32_t aBase = smem_base + SM_A + a_row0 * 256;
    const int a_ph = a_row0 & 7;
    const int b_ph = b_row0 & 7;

    const int gid = lane >> 2, tig = lane & 3;

#pragma unroll
    for (int nt = 0; nt < 4; nt++) {
        // Prefetch B for tile nt+1 into the other buffer (overwrites the
        // buffer last read at nt-1; safe: sync at end of that mainloop).
        if (nt < 3) {
            const uint32_t dstb = ((nt + 1) & 1) ? (uint32_t)SM_B1 : (uint32_t)SM_B0;
            const int nrow0 = nb0 + (nt + 1) * TILE;
#pragma unroll
            for (int it = 0; it < 8; it++) {
                int u = tid + 256 * it;
                int row = u >> 4, cu = u & 15;
                const uint4* src = (const uint4*)g_yb + (size_t)(nrow0 + row) * 16 + cu;
                cp16(smem_base + dstb + row * 256 + ((cu ^ (row & 7)) << 4), src);
            }
            asm volatile("cp.async.commit_group;" ::: "memory");
            asm volatile("cp.async.wait_group 1;" ::: "memory");
        } else {
            asm volatile("cp.async.wait_group 0;" ::: "memory");
        }
        __syncthreads();

        const uint32_t bBase = smem_base + ((nt & 1) ? SM_B1 : SM_B0) + b_row0 * 256;

        float acc[4][4][4];
#pragma unroll
        for (int ti = 0; ti < 4; ti++)
#pragma unroll
            for (int j = 0; j < 4; j++)
#pragma unroll
                for (int r = 0; r < 4; r++) acc[ti][j][r] = 0.f;

#pragma unroll
        for (int ks = 0; ks < 8; ks++) {
            const uint32_t aoff = (uint32_t)(((ks * 2 + a_sel) ^ a_ph) << 4);
            const uint32_t boff = (uint32_t)(((ks * 2 + b_sel) ^ b_ph) << 4);
            uint32_t b0[4], b1[4];
            ldsm4(b0, bBase + boff);
            ldsm4(b1, bBase + 16 * 256 + boff);
#pragma unroll
            for (int ti = 0; ti < 4; ti++) {
                uint32_t a[4];
                ldsm4(a, aBase + ti * (16 * 256) + aoff);
                mma16(acc[ti][0], a, b0[0], b0[1]);
                mma16(acc[ti][1], a, b0[2], b0[3]);
                mma16(acc[ti][2], a, b1[0], b1[1]);
                mma16(acc[ti][3], a, b1[2], b1[3]);
            }
        }
        __syncthreads();   // all warps done reading this B buffer

        // Epilogue for tile nt.
        const int mrow_base = m0 + w_m * 64;
#pragma unroll
        for (int ti = 0; ti < 4; ti++) {
#pragma unroll
            for (int h = 0; h < 2; h++) {
                const int m = mrow_base + ti * 16 + h * 8 + gid;
                const float xv = 0.5f * g_x2[m];
                float* orow = out + (size_t)m * NROWS + nb0 + nt * TILE + w_n * 32 + tig * 2;
#pragma unroll
                for (int j = 0; j < 4; j++) {
                    const int col = nt * TILE + w_n * 32 + j * 8 + tig * 2;
                    float2 o;
                    o.x = xv + ys[col + 0] - acc[ti][j][h * 2 + 0];
                    o.y = xv + ys[col + 1] - acc[ti][j][h * 2 + 1];
                    *(float2*)(orow + j * 8) = o;
                }
            }
        }
    }
}

// ---- launch ----
extern "C" void kernel_launch(void* const* d_in, const int* in_sizes, int n_in,
                              void* d_out, int out_size) {
    const float* x = (const float*)d_in[0];
    const float* y = (const float*)d_in[1];
    float* out = (float*)d_out;

    cudaFuncSetAttribute(cost_kernel, cudaFuncAttributeMaxDynamicSharedMemorySize, SM_TOTAL);

    prep_kernel<<<(2 * NROWS * 32) / 256, 256>>>(x, y);
    dim3 grid(NROWS / 512, NROWS / TILE);   // (8, 32) = 256 CTAs
    cost_kernel<<<grid, 256, SM_TOTAL>>>(out);
}

// round 17
// speedup vs baseline: 1.1686x; 1.0588x over previous
#include <cuda_runtime.h>
#include <cuda_bf16.h>
#include <cstdint>

// costs[0,i,j] = 0.5*(|x_i|^2 + |y_j|^2) - x_i . y_j
// x: [1,4096,128] f32, y: [1,4096,128] f32, out: [1,4096,4096] f32.
//
// bf16 mma.sync m16n8k16 + ldmatrix, swizzled smem, pre-converted bf16.
// 128x64 CTA tile, 256 thr / 8 warps x (32x32), acc=32 regs -> fits
// 3 CTAs/SM (85-reg cap) WITHOUT spills: 24 warps/SM for latency hiding.

#define NROWS 4096
#define DK    128

static __device__ float g_x2[NROWS];
static __device__ float g_y2[NROWS];
static __device__ __align__(16) __nv_bfloat16 g_xb[NROWS * DK];
static __device__ __align__(16) __nv_bfloat16 g_yb[NROWS * DK];

// ---- helpers ----
__device__ __forceinline__ uint32_t pack_bf16x2(float a, float b) {
    uint32_t r;
    asm("cvt.rn.bf16x2.f32 %0, %1, %2;" : "=r"(r) : "f"(b), "f"(a));
    return r;
}

__device__ __forceinline__ uint32_t smem_u32(const void* p) {
    uint32_t a;
    asm("{ .reg .u64 t; cvta.to.shared.u64 t, %1; cvt.u32.u64 %0, t; }" : "=r"(a) : "l"(p));
    return a;
}

__device__ __forceinline__ void ldsm4(uint32_t* r, uint32_t addr) {
    asm volatile("ldmatrix.sync.aligned.m8n8.x4.shared.b16 {%0,%1,%2,%3}, [%4];"
                 : "=r"(r[0]), "=r"(r[1]), "=r"(r[2]), "=r"(r[3]) : "r"(addr));
}

__device__ __forceinline__ void mma16(float* d, const uint32_t* a, uint32_t b0, uint32_t b1) {
    asm volatile(
        "mma.sync.aligned.m16n8k16.row.col.f32.bf16.bf16.f32 "
        "{%0,%1,%2,%3}, {%4,%5,%6,%7}, {%8,%9}, {%0,%1,%2,%3};"
        : "+f"(d[0]), "+f"(d[1]), "+f"(d[2]), "+f"(d[3])
        : "r"(a[0]), "r"(a[1]), "r"(a[2]), "r"(a[3]), "r"(b0), "r"(b1));
}

__device__ __forceinline__ void cp16(uint32_t dst, const void* src) {
    asm volatile("cp.async.cg.shared.global [%0], [%1], 16;" :: "r"(dst), "l"(src) : "memory");
}

// ---- smem layout (bytes) ----
// ys (64 f32) @0 ; A tile 128x128bf16 @512 (32KB) ; B tile 64x128bf16 @+32KB.
#define SM_YS    0
#define SM_A     512
#define SM_B     (512 + 128 * 256)
#define SM_TOTAL (SM_B + 64 * 256)        // 49664 B -> 3 CTAs/SM

// ---- pre-kernel: row norms + bf16 conversion (one pass) ----
__global__ void prep_kernel(const float* __restrict__ x, const float* __restrict__ y) {
    int gid = blockIdx.x * blockDim.x + threadIdx.x;
    int row = gid >> 5;
    int lane = gid & 31;
    bool isx = row < NROWS;
    int r = isx ? row : row - NROWS;
    const float4 v = ((const float4*)(isx ? x : y))[(size_t)r * 32 + lane];
    float s = v.x * v.x + v.y * v.y + v.z * v.z + v.w * v.w;
#pragma unroll
    for (int o = 16; o; o >>= 1) s += __shfl_xor_sync(0xffffffffu, s, o);
    uint2 w;
    w.x = pack_bf16x2(v.x, v.y);
    w.y = pack_bf16x2(v.z, v.w);
    ((uint2*)(isx ? g_xb : g_yb))[(size_t)r * 32 + lane] = w;
    if (lane == 0) { if (isx) g_x2[r] = s; else g_y2[r] = s; }
}

// ---- main kernel: 128x64 tile/CTA, 8 warps (4M x 2N of 32x32), 3 CTAs/SM ----
__global__ void __launch_bounds__(256, 3)
cost_kernel(float* __restrict__ out) {
    extern __shared__ char smem[];
    float* ys = (float*)(smem + SM_YS);
    const uint32_t smem_base = smem_u32(smem);

    const int tid = threadIdx.x;
    const int wid = tid >> 5;
    const int lane = tid & 31;

    const int m0 = blockIdx.y * 128;
    const int n0 = blockIdx.x * 64;

    if (tid < 64) ys[tid] = 0.5f * g_y2[n0 + tid];

    // Fill via cp.async: A = 2048 16B units, B = 1024 units; 256 thr.
#pragma unroll
    for (int it = 0; it < 8; it++) {
        int u = tid + 256 * it;                // 0..2047
        int row = u >> 4, cu = u & 15;
        const uint4* src = (const uint4*)g_xb + (size_t)(m0 + row) * 16 + cu;
        cp16(smem_base + SM_A + row * 256 + ((cu ^ (row & 7)) << 4), src);
    }
#pragma unroll
    for (int it = 0; it < 4; it++) {
        int u = tid + 256 * it;                // 0..1023
        int row = u >> 4, cu = u & 15;
        const uint4* src = (const uint4*)g_yb + (size_t)(n0 + row) * 16 + cu;
        cp16(smem_base + SM_B + row * 256 + ((cu ^ (row & 7)) << 4), src);
    }
    asm volatile("cp.async.commit_group;" ::: "memory");
    asm volatile("cp.async.wait_group 0;" ::: "memory");
    __syncthreads();

    // Warp tiling: w_m 0..3 (32 rows), w_n 0..1 (32 cols)
    const int w_m = wid >> 1, w_n = wid & 1;

    const int a_row0 = w_m * 32 + (lane & 7) + ((lane >> 3) & 1) * 8;
    const int a_sel  = lane >> 4;
    const int b_row0 = w_n * 32 + (lane & 7) + (lane >> 4) * 8;
    const int b_sel  = (lane >> 3) & 1;

    const uint32_t aBase = smem_base + SM_A + a_row0 * 256;
    const uint32_t bBase = smem_base + SM_B + b_row0 * 256;
    const int a_ph = a_row0 & 7;
    const int b_ph = b_row0 & 7;

    float acc[2][4][4];
#pragma unroll
    for (int ti = 0; ti < 2; ti++)
#pragma unroll
        for (int j = 0; j < 4; j++)
#pragma unroll
            for (int r = 0; r < 4; r++) acc[ti][j][r] = 0.f;

    // Mainloop: per ks load B (2 x4 = 4 n-tiles' frags), stream A per-ti.
#pragma unroll
    for (int ks = 0; ks < 8; ks++) {
        const uint32_t aoff = (uint32_t)(((ks * 2 + a_sel) ^ a_ph) << 4);
        const uint32_t boff = (uint32_t)(((ks * 2 + b_sel) ^ b_ph) << 4);
        uint32_t b0[4], b1[4];
        ldsm4(b0, bBase + boff);               // n-tiles 0,1 (cols w_n*32+0..15)
        ldsm4(b1, bBase + 16 * 256 + boff);    // n-tiles 2,3 (cols w_n*32+16..31)
#pragma unroll
        for (int ti = 0; ti < 2; ti++) {
            uint32_t a[4];
            ldsm4(a, aBase + ti * (16 * 256) + aoff);
            mma16(acc[ti][0], a, b0[0], b0[1]);
            mma16(acc[ti][1], a, b0[2], b0[3]);
            mma16(acc[ti][2], a, b1[0], b1[1]);
            mma16(acc[ti][3], a, b1[2], b1[3]);
        }
    }

    // Epilogue: acc[ti][j] -> rows w_m*32+ti*16+{0,8}+gid, cols w_n*32+j*8+2*tig
    const int gid = lane >> 2, tig = lane & 3;
    const int mrow_base = m0 + w_m * 32;

#pragma unroll
    for (int ti = 0; ti < 2; ti++) {
#pragma unroll
        for (int h = 0; h < 2; h++) {
            const int m = mrow_base + ti * 16 + h * 8 + gid;
            const float xv = 0.5f * g_x2[m];
            float* orow = out + (size_t)m * NROWS + n0 + w_n * 32 + tig * 2;
#pragma unroll
            for (int j = 0; j < 4; j++) {
                const int col = w_n * 32 + j * 8 + tig * 2;
                float2 o;
                o.x = xv + ys[col + 0] - acc[ti][j][h * 2 + 0];
                o.y = xv + ys[col + 1] - acc[ti][j][h * 2 + 1];
                *(float2*)(orow + j * 8) = o;
            }
        }
    }
}

// ---- launch ----
extern "C" void kernel_launch(void* const* d_in, const int* in_sizes, int n_in,
                              void* d_out, int out_size) {
    const float* x = (const float*)d_in[0];
    const float* y = (const float*)d_in[1];
    float* out = (float*)d_out;

    cudaFuncSetAttribute(cost_kernel, cudaFuncAttributeMaxDynamicSharedMemorySize, SM_TOTAL);

    prep_kernel<<<(2 * NROWS * 32) / 256, 256>>>(x, y);
    dim3 grid(NROWS / 64, NROWS / 128);   // (64, 32) = 2048 CTAs
    cost_kernel<<<grid, 256, SM_TOTAL>>>(out);
}